// round 8
// baseline (speedup 1.0000x reference)
#include <cuda_runtime.h>
#include <cuda_fp16.h>

#define N_NODES 100000
#define E_EDGES 1600000
#define D 64

// Scratch
__device__ __half2 g_xh[N_NODES * 32];       // fp16 copy of x (12.8 MB)
__device__ int g_cnt[3][N_NODES];            // per-etype in-degree (hist)
__device__ int g_cursor[3][N_NODES];         // excl. start -> (post-scatter) end
__device__ int g_bucket[3][E_EDGES];         // dense CSR src ids (19.2 MB)
__device__ float g_mean[N_NODES * 192];      // per-etype means, fp32 (76.8 MB)

// ---------------------------------------------------------------------------
// Prep: x -> half2 copy, zero histograms.
// ---------------------------------------------------------------------------
__global__ __launch_bounds__(256) void k_prep(const float2* __restrict__ x2) {
    int idx = blockIdx.x * blockDim.x + threadIdx.x;
    int stride = gridDim.x * blockDim.x;
    const int nh = N_NODES * 32;
    for (int i = idx; i < nh; i += stride) {
        float2 v = x2[i];
        g_xh[i] = __floats2half2_rn(v.x, v.y);
    }
    int* cnt = &g_cnt[0][0];
    for (int i = idx; i < 3 * N_NODES; i += stride) cnt[i] = 0;
}

// ---------------------------------------------------------------------------
__global__ __launch_bounds__(256) void k_hist(
    const int* __restrict__ d0, const int* __restrict__ d1,
    const int* __restrict__ d2)
{
    int e = blockIdx.y;
    const int* __restrict__ dst = (e == 0) ? d0 : (e == 1) ? d1 : d2;
    int* hist = g_cnt[e];
    int idx = blockIdx.x * blockDim.x + threadIdx.x;
    int stride = gridDim.x * blockDim.x;
    for (int i = idx; i < E_EDGES; i += stride)
        atomicAdd(hist + __ldg(&dst[i]), 1);
}

// ---------------------------------------------------------------------------
// One block per etype: chunked exclusive scan of g_cnt -> g_cursor.
// ---------------------------------------------------------------------------
__global__ __launch_bounds__(1024) void k_scan() {
    __shared__ int wsum[32];
    __shared__ int carry;
    int e = blockIdx.x;
    int lane = threadIdx.x & 31;
    int wid  = threadIdx.x >> 5;
    if (threadIdx.x == 0) carry = 0;
    __syncthreads();

    for (int base = 0; base < N_NODES; base += 1024) {
        int c0 = carry;
        int n = base + threadIdx.x;
        int v = (n < N_NODES) ? g_cnt[e][n] : 0;
        int sc = v;
        #pragma unroll
        for (int d = 1; d < 32; d <<= 1) {
            int t = __shfl_up_sync(0xffffffffu, sc, d);
            if (lane >= d) sc += t;
        }
        if (lane == 31) wsum[wid] = sc;
        __syncthreads();
        if (wid == 0) {
            int s = wsum[lane];
            #pragma unroll
            for (int d = 1; d < 32; d <<= 1) {
                int t = __shfl_up_sync(0xffffffffu, s, d);
                if (lane >= d) s += t;
            }
            wsum[lane] = s;
        }
        __syncthreads();
        int inc = sc + (wid > 0 ? wsum[wid - 1] : 0);
        if (n < N_NODES) g_cursor[e][n] = c0 + inc - v;
        __syncthreads();
        if (threadIdx.x == 1023) carry = c0 + inc;
        __syncthreads();
    }
}

// ---------------------------------------------------------------------------
__global__ __launch_bounds__(256) void k_scatter(
    const int* __restrict__ s0, const int* __restrict__ d0,
    const int* __restrict__ s1, const int* __restrict__ d1,
    const int* __restrict__ s2, const int* __restrict__ d2)
{
    int e = blockIdx.y;
    const int* __restrict__ src = (e == 0) ? s0 : (e == 1) ? s1 : s2;
    const int* __restrict__ dst = (e == 0) ? d0 : (e == 1) ? d1 : d2;
    int* cursor = g_cursor[e];
    int* bucket = g_bucket[e];
    int idx = blockIdx.x * blockDim.x + threadIdx.x;
    int stride = gridDim.x * blockDim.x;
    for (int i = idx; i < E_EDGES; i += stride) {
        int d = __ldg(&dst[i]);
        int pos = atomicAdd(cursor + d, 1);
        bucket[pos] = __ldg(&src[i]);
    }
}

// ---------------------------------------------------------------------------
// Gather + mean only. One warp per node; lane l owns mean cols 2l, 2l+1.
// Writes g_mean[n][e*64 + c] fp32, zeros when deg==0.
// ---------------------------------------------------------------------------
__global__ __launch_bounds__(256) void k_mean() {
    int tid  = threadIdx.x;
    int lane = tid & 31;
    int wid  = tid >> 5;
    int gw = blockIdx.x * 8 + wid;
    int nwarps = gridDim.x * 8;

    for (int n = gw; n < N_NODES; n += nwarps) {
        #pragma unroll
        for (int e = 0; e < 3; e++) {
            int end = g_cursor[e][n];
            int cnt = g_cnt[e][n];
            float a0 = 0.f, a1 = 0.f;
            if (cnt > 0) {
                int beg = end - cnt;
                const int* __restrict__ bk = g_bucket[e];
                int i = beg;
                for (; i + 32 <= end; i += 32) {
                    int myid = __ldg(&bk[i + lane]);
                    #pragma unroll 8
                    for (int j = 0; j < 32; j++) {
                        int s = __shfl_sync(0xffffffffu, myid, j);
                        float2 f = __half22float2(g_xh[s * 32 + lane]);
                        a0 += f.x; a1 += f.y;
                    }
                }
                if (i < end) {
                    int m = end - i;
                    int myid = (i + lane < end) ? __ldg(&bk[i + lane]) : 0;
                    for (int j = 0; j < m; j++) {
                        int s = __shfl_sync(0xffffffffu, myid, j);
                        float2 f = __half22float2(g_xh[s * 32 + lane]);
                        a0 += f.x; a1 += f.y;
                    }
                }
                float inv = 1.0f / (float)cnt;
                a0 *= inv; a1 *= inv;
            }
            *reinterpret_cast<float2*>(g_mean + n * 192 + e * 64 + 2 * lane) =
                make_float2(a0, a1);
        }
    }
}

// ---------------------------------------------------------------------------
// Tiled GEMM: out[32-node tile] = Mtile[32x192] @ Wcat[192x64] + masked bias.
// W staged once per block. Means staged transposed (stride 36), loaded with
// oct-strided k assignment (bank-conflict-free, coalesced GMEM reads).
// Thread (c2 = 2*(tid&31), g = tid>>5): 4 nodes x 2 cols.
// ---------------------------------------------------------------------------
__global__ __launch_bounds__(256) void k_gemm(
    const float* __restrict__ W0, const float* __restrict__ b0,
    const float* __restrict__ W1, const float* __restrict__ b1,
    const float* __restrict__ W2, const float* __restrict__ b2,
    float* __restrict__ out)
{
    extern __shared__ float sm[];
    float* Wsh = sm;                // 3*4096 = 12288
    float* bsh = sm + 12288;        // 192
    float* ash = sm + 12480;        // 192 * 36 = 6912, [k][node] stride 36
    float* msk = sm + 19392;        // 3 * 32

    int tid = threadIdx.x;
    int tile0 = blockIdx.x * 32;

    for (int i = tid; i < 4096; i += 256) {
        Wsh[i]        = W0[i];
        Wsh[4096 + i] = W1[i];
        Wsh[8192 + i] = W2[i];
    }
    if (tid < 64) {
        bsh[tid]       = b0[tid];
        bsh[64 + tid]  = b1[tid];
        bsh[128 + tid] = b2[tid];
    }
    if (tid < 32) {
        int node = tile0 + tid;
        #pragma unroll
        for (int e = 0; e < 3; e++)
            msk[e * 32 + tid] = (g_cnt[e][node] > 0) ? 1.f : 0.f;
    }

    // stage means transposed: thread (i = tid>>3, oct = tid&7) loads
    // k = oct + 8*m, m = 0..23 (warp reads 32B-sector-contiguous per node).
    {
        int i   = tid >> 3;
        int oct = tid & 7;
        const float* mrow = g_mean + (tile0 + i) * 192;
        #pragma unroll 8
        for (int m = 0; m < 24; m++) {
            int k = oct + 8 * m;
            ash[k * 36 + i] = __ldg(&mrow[k]);
        }
    }
    __syncthreads();

    int c2 = (tid & 31) * 2;
    int g  = tid >> 5;          // uniform per warp
    float2 o0 = {0.f, 0.f}, o1 = {0.f, 0.f}, o2 = {0.f, 0.f}, o3 = {0.f, 0.f};

    #pragma unroll
    for (int e = 0; e < 3; e++) {
        const float* We = Wsh + e * 4096 + c2;
        const float* A  = ash + e * 64 * 36 + g * 4;
        #pragma unroll 16
        for (int k = 0; k < 64; k++) {
            float4 a = *reinterpret_cast<const float4*>(A + k * 36);
            float2 w = *reinterpret_cast<const float2*>(We + k * 64);
            o0.x += a.x * w.x; o0.y += a.x * w.y;
            o1.x += a.y * w.x; o1.y += a.y * w.y;
            o2.x += a.z * w.x; o2.y += a.z * w.y;
            o3.x += a.w * w.x; o3.y += a.w * w.y;
        }
    }

    float bx[4] = {0.f, 0.f, 0.f, 0.f};
    float by[4] = {0.f, 0.f, 0.f, 0.f};
    #pragma unroll
    for (int e = 0; e < 3; e++) {
        float wb0 = bsh[e * 64 + c2];
        float wb1 = bsh[e * 64 + c2 + 1];
        #pragma unroll
        for (int j = 0; j < 4; j++) {
            float mk = msk[e * 32 + g * 4 + j];
            bx[j] += mk * wb0;
            by[j] += mk * wb1;
        }
    }

    float2 oo[4] = {o0, o1, o2, o3};
    #pragma unroll
    for (int j = 0; j < 4; j++) {
        int node = tile0 + g * 4 + j;
        *reinterpret_cast<float2*>(out + node * 64 + c2) =
            make_float2(oo[j].x + bx[j], oo[j].y + by[j]);
    }
}

// ---------------------------------------------------------------------------
extern "C" void kernel_launch(void* const* d_in, const int* in_sizes, int n_in,
                              void* d_out, int out_size)
{
    const float* x  = (const float*)d_in[0];
    const float* W0 = (const float*)d_in[1];
    const float* b0 = (const float*)d_in[2];
    const int*   s0 = (const int*)  d_in[3];
    const int*   t0 = (const int*)  d_in[4];
    const float* W1 = (const float*)d_in[5];
    const float* b1 = (const float*)d_in[6];
    const int*   s1 = (const int*)  d_in[7];
    const int*   t1 = (const int*)  d_in[8];
    const float* W2 = (const float*)d_in[9];
    const float* b2 = (const float*)d_in[10];
    const int*   s2 = (const int*)  d_in[11];
    const int*   t2 = (const int*)  d_in[12];
    float* out = (float*)d_out;

    k_prep<<<1024, 256>>>(reinterpret_cast<const float2*>(x));

    dim3 gE(1184, 3);
    k_hist<<<gE, 256>>>(t0, t1, t2);
    k_scan<<<3, 1024>>>();
    k_scatter<<<gE, 256>>>(s0, t0, s1, t1, s2, t2);

    k_mean<<<1184, 256>>>();

    cudaFuncSetAttribute(k_gemm,
                         cudaFuncAttributeMaxDynamicSharedMemorySize, 78400);
    k_gemm<<<N_NODES / 32, 256, 19488 * sizeof(float)>>>(
        W0, b0, W1, b1, W2, b2, out);
}

// round 9
// speedup vs baseline: 1.0208x; 1.0208x over previous
#include <cuda_runtime.h>
#include <cuda_fp16.h>

#define N_NODES 100000
#define E_EDGES 1600000
#define D 64

// Scratch
__device__ __half2 g_xh[N_NODES * 32];       // fp16 copy of x (12.8 MB)
__device__ int g_cnt[3][N_NODES];            // per-etype in-degree (hist)
__device__ int g_cursor[3][N_NODES];         // excl. start -> (post-scatter) end
__device__ int g_bucket[3][E_EDGES];         // dense CSR src ids (19.2 MB)
__device__ float g_mean[N_NODES * 192];      // per-etype means, fp32 (76.8 MB)

// ---------------------------------------------------------------------------
__global__ __launch_bounds__(256) void k_prep(const float2* __restrict__ x2) {
    int idx = blockIdx.x * blockDim.x + threadIdx.x;
    int stride = gridDim.x * blockDim.x;
    const int nh = N_NODES * 32;
    for (int i = idx; i < nh; i += stride) {
        float2 v = x2[i];
        g_xh[i] = __floats2half2_rn(v.x, v.y);
    }
    int* cnt = &g_cnt[0][0];
    for (int i = idx; i < 3 * N_NODES; i += stride) cnt[i] = 0;
}

// ---------------------------------------------------------------------------
// Histogram: 4 independent edges per thread per iteration (int4 loads).
// ---------------------------------------------------------------------------
__global__ __launch_bounds__(256) void k_hist(
    const int4* __restrict__ d0, const int4* __restrict__ d1,
    const int4* __restrict__ d2)
{
    int e = blockIdx.y;
    const int4* __restrict__ dst4 = (e == 0) ? d0 : (e == 1) ? d1 : d2;
    int* hist = g_cnt[e];
    int idx = blockIdx.x * blockDim.x + threadIdx.x;
    int stride = gridDim.x * blockDim.x;
    const int n4 = E_EDGES / 4;
    for (int i = idx; i < n4; i += stride) {
        int4 d = __ldg(&dst4[i]);
        atomicAdd(hist + d.x, 1);
        atomicAdd(hist + d.y, 1);
        atomicAdd(hist + d.z, 1);
        atomicAdd(hist + d.w, 1);
    }
}

// ---------------------------------------------------------------------------
// One block per etype: chunked exclusive scan of g_cnt -> g_cursor.
// ---------------------------------------------------------------------------
__global__ __launch_bounds__(1024) void k_scan() {
    __shared__ int wsum[32];
    __shared__ int carry;
    int e = blockIdx.x;
    int lane = threadIdx.x & 31;
    int wid  = threadIdx.x >> 5;
    if (threadIdx.x == 0) carry = 0;
    __syncthreads();

    for (int base = 0; base < N_NODES; base += 1024) {
        int c0 = carry;
        int n = base + threadIdx.x;
        int v = (n < N_NODES) ? g_cnt[e][n] : 0;
        int sc = v;
        #pragma unroll
        for (int d = 1; d < 32; d <<= 1) {
            int t = __shfl_up_sync(0xffffffffu, sc, d);
            if (lane >= d) sc += t;
        }
        if (lane == 31) wsum[wid] = sc;
        __syncthreads();
        if (wid == 0) {
            int s = wsum[lane];
            #pragma unroll
            for (int d = 1; d < 32; d <<= 1) {
                int t = __shfl_up_sync(0xffffffffu, s, d);
                if (lane >= d) s += t;
            }
            wsum[lane] = s;
        }
        __syncthreads();
        int inc = sc + (wid > 0 ? wsum[wid - 1] : 0);
        if (n < N_NODES) g_cursor[e][n] = c0 + inc - v;
        __syncthreads();
        if (threadIdx.x == 1023) carry = c0 + inc;
        __syncthreads();
    }
}

// ---------------------------------------------------------------------------
// Scatter: 4 independent edges per thread per iteration.
// ---------------------------------------------------------------------------
__global__ __launch_bounds__(256) void k_scatter(
    const int4* __restrict__ s0, const int4* __restrict__ d0,
    const int4* __restrict__ s1, const int4* __restrict__ d1,
    const int4* __restrict__ s2, const int4* __restrict__ d2)
{
    int e = blockIdx.y;
    const int4* __restrict__ src4 = (e == 0) ? s0 : (e == 1) ? s1 : s2;
    const int4* __restrict__ dst4 = (e == 0) ? d0 : (e == 1) ? d1 : d2;
    int* cursor = g_cursor[e];
    int* bucket = g_bucket[e];
    int idx = blockIdx.x * blockDim.x + threadIdx.x;
    int stride = gridDim.x * blockDim.x;
    const int n4 = E_EDGES / 4;
    for (int i = idx; i < n4; i += stride) {
        int4 d = __ldg(&dst4[i]);
        int4 s = __ldg(&src4[i]);
        int p0 = atomicAdd(cursor + d.x, 1);
        int p1 = atomicAdd(cursor + d.y, 1);
        int p2 = atomicAdd(cursor + d.z, 1);
        int p3 = atomicAdd(cursor + d.w, 1);
        bucket[p0] = s.x;
        bucket[p1] = s.y;
        bucket[p2] = s.z;
        bucket[p3] = s.w;
    }
}

// ---------------------------------------------------------------------------
// Gather + mean: TWO nodes per warp (16 lanes each). Lane = (sub, hl):
// sub = node within warp, hl owns cols 4hl..4hl+3 (8 B per x row load).
// ---------------------------------------------------------------------------
__global__ __launch_bounds__(256) void k_mean() {
    int tid  = threadIdx.x;
    int lane = tid & 31;
    int wid  = tid >> 5;
    int sub  = lane >> 4;
    int hl   = lane & 15;
    int b16  = sub << 4;
    unsigned hm = 0xFFFFu << b16;

    int gw = blockIdx.x * 8 + wid;
    int nwarps = gridDim.x * 8;

    for (int nb = gw * 2; nb < N_NODES; nb += nwarps * 2) {
        int n = nb + sub;          // N even, nwarps*2 even -> always < N
        #pragma unroll
        for (int e = 0; e < 3; e++) {
            int end = g_cursor[e][n];
            int cnt = g_cnt[e][n];
            int beg = end - cnt;
            const int* __restrict__ bk = g_bucket[e];

            float a0 = 0.f, a1 = 0.f, a2 = 0.f, a3 = 0.f;
            int i = beg;
            for (; i + 16 <= end; i += 16) {
                int id = __ldg(&bk[i + hl]);
                #pragma unroll 4
                for (int j = 0; j < 16; j++) {
                    int s = __shfl_sync(hm, id, b16 + j);
                    uint2 v = *reinterpret_cast<const uint2*>(g_xh + s * 32 + 2 * hl);
                    float2 f0 = __half22float2(*reinterpret_cast<__half2*>(&v.x));
                    float2 f1 = __half22float2(*reinterpret_cast<__half2*>(&v.y));
                    a0 += f0.x; a1 += f0.y; a2 += f1.x; a3 += f1.y;
                }
            }
            if (i < end) {
                int m = end - i;
                int id = (hl < m) ? __ldg(&bk[i + hl]) : 0;
                for (int j = 0; j < m; j++) {
                    int s = __shfl_sync(hm, id, b16 + j);
                    uint2 v = *reinterpret_cast<const uint2*>(g_xh + s * 32 + 2 * hl);
                    float2 f0 = __half22float2(*reinterpret_cast<__half2*>(&v.x));
                    float2 f1 = __half22float2(*reinterpret_cast<__half2*>(&v.y));
                    a0 += f0.x; a1 += f0.y; a2 += f1.x; a3 += f1.y;
                }
            }
            float inv = (cnt > 0) ? (1.0f / (float)cnt) : 0.f;
            *reinterpret_cast<float4*>(g_mean + (size_t)n * 192 + e * 64 + 4 * hl) =
                make_float4(a0 * inv, a1 * inv, a2 * inv, a3 * inv);
        }
    }
}

// ---------------------------------------------------------------------------
// Tiled GEMM: 160-node tile (625 blocks x 160 = N exactly), 320 threads.
// Thread = (g = tid>>4 : 8-node group, c4 = (tid&15)*4 : 4 cols).
// ash = means transposed [k][node], stride 164 (bank-safe). W staged once.
// ---------------------------------------------------------------------------
#define TILE_N 160
#define ASTRIDE 164

__global__ __launch_bounds__(320) void k_gemm(
    const float* __restrict__ W0, const float* __restrict__ b0,
    const float* __restrict__ W1, const float* __restrict__ b1,
    const float* __restrict__ W2, const float* __restrict__ b2,
    float* __restrict__ out)
{
    extern __shared__ float sm[];
    float* Wsh = sm;                   // 12288
    float* bsh = sm + 12288;           // 192
    float* ash = sm + 12480;           // 192 * 164 = 31488
    float* msk = sm + 43968;           // 3 * 160

    int tid = threadIdx.x;
    int tile0 = blockIdx.x * TILE_N;

    for (int i = tid; i < 4096; i += 320) {
        Wsh[i]        = W0[i];
        Wsh[4096 + i] = W1[i];
        Wsh[8192 + i] = W2[i];
    }
    if (tid < 64) {
        bsh[tid]       = b0[tid];
        bsh[64 + tid]  = b1[tid];
        bsh[128 + tid] = b2[tid];
    }
    if (tid < TILE_N) {
        #pragma unroll
        for (int e = 0; e < 3; e++)
            msk[e * TILE_N + tid] = (g_cnt[e][tile0 + tid] > 0) ? 1.f : 0.f;
    }

    // stage means transposed: 2 threads per node, each streams 96 contiguous
    // floats (24 x LDG.128) of its half of the 192-row.
    {
        int node = tid >> 1;
        int kh   = tid & 1;
        const float4* mrow = reinterpret_cast<const float4*>(
            g_mean + (size_t)(tile0 + node) * 192 + kh * 96);
        #pragma unroll 6
        for (int m = 0; m < 24; m++) {
            float4 v = __ldg(&mrow[m]);
            int k = kh * 96 + m * 4;
            ash[(k + 0) * ASTRIDE + node] = v.x;
            ash[(k + 1) * ASTRIDE + node] = v.y;
            ash[(k + 2) * ASTRIDE + node] = v.z;
            ash[(k + 3) * ASTRIDE + node] = v.w;
        }
    }
    __syncthreads();

    int c4 = (tid & 15) * 4;
    int g  = tid >> 4;                 // 0..19
    float4 acc[8];
    #pragma unroll
    for (int j = 0; j < 8; j++) acc[j] = make_float4(0.f, 0.f, 0.f, 0.f);

    #pragma unroll
    for (int e = 0; e < 3; e++) {
        const float* A  = ash + e * 64 * ASTRIDE + g * 8;
        const float* We = Wsh + e * 4096 + c4;
        #pragma unroll 8
        for (int k = 0; k < 64; k++) {
            float4 a0 = *reinterpret_cast<const float4*>(A + k * ASTRIDE);
            float4 a1 = *reinterpret_cast<const float4*>(A + k * ASTRIDE + 4);
            float4 w  = *reinterpret_cast<const float4*>(We + k * 64);
            acc[0].x += a0.x * w.x; acc[0].y += a0.x * w.y; acc[0].z += a0.x * w.z; acc[0].w += a0.x * w.w;
            acc[1].x += a0.y * w.x; acc[1].y += a0.y * w.y; acc[1].z += a0.y * w.z; acc[1].w += a0.y * w.w;
            acc[2].x += a0.z * w.x; acc[2].y += a0.z * w.y; acc[2].z += a0.z * w.z; acc[2].w += a0.z * w.w;
            acc[3].x += a0.w * w.x; acc[3].y += a0.w * w.y; acc[3].z += a0.w * w.z; acc[3].w += a0.w * w.w;
            acc[4].x += a1.x * w.x; acc[4].y += a1.x * w.y; acc[4].z += a1.x * w.z; acc[4].w += a1.x * w.w;
            acc[5].x += a1.y * w.x; acc[5].y += a1.y * w.y; acc[5].z += a1.y * w.z; acc[5].w += a1.y * w.w;
            acc[6].x += a1.z * w.x; acc[6].y += a1.z * w.y; acc[6].z += a1.z * w.z; acc[6].w += a1.z * w.w;
            acc[7].x += a1.w * w.x; acc[7].y += a1.w * w.y; acc[7].z += a1.w * w.z; acc[7].w += a1.w * w.w;
        }
    }

    // bias (masked) + writeback
    float4 bias[3];
    #pragma unroll
    for (int e = 0; e < 3; e++)
        bias[e] = *reinterpret_cast<const float4*>(bsh + e * 64 + c4);

    #pragma unroll
    for (int j = 0; j < 8; j++) {
        int node = tile0 + g * 8 + j;
        float4 r = acc[j];
        #pragma unroll
        for (int e = 0; e < 3; e++) {
            float mk = msk[e * TILE_N + g * 8 + j];
            r.x += mk * bias[e].x;
            r.y += mk * bias[e].y;
            r.z += mk * bias[e].z;
            r.w += mk * bias[e].w;
        }
        *reinterpret_cast<float4*>(out + (size_t)node * 64 + c4) = r;
    }
}

// ---------------------------------------------------------------------------
extern "C" void kernel_launch(void* const* d_in, const int* in_sizes, int n_in,
                              void* d_out, int out_size)
{
    const float* x  = (const float*)d_in[0];
    const float* W0 = (const float*)d_in[1];
    const float* b0 = (const float*)d_in[2];
    const int*   s0 = (const int*)  d_in[3];
    const int*   t0 = (const int*)  d_in[4];
    const float* W1 = (const float*)d_in[5];
    const float* b1 = (const float*)d_in[6];
    const int*   s1 = (const int*)  d_in[7];
    const int*   t1 = (const int*)  d_in[8];
    const float* W2 = (const float*)d_in[9];
    const float* b2 = (const float*)d_in[10];
    const int*   s2 = (const int*)  d_in[11];
    const int*   t2 = (const int*)  d_in[12];
    float* out = (float*)d_out;

    k_prep<<<1024, 256>>>(reinterpret_cast<const float2*>(x));

    dim3 gE(782, 3);
    k_hist<<<gE, 256>>>((const int4*)t0, (const int4*)t1, (const int4*)t2);
    k_scan<<<3, 1024>>>();
    k_scatter<<<gE, 256>>>((const int4*)s0, (const int4*)t0,
                           (const int4*)s1, (const int4*)t1,
                           (const int4*)s2, (const int4*)t2);

    k_mean<<<1184, 256>>>();

    cudaFuncSetAttribute(k_gemm,
                         cudaFuncAttributeMaxDynamicSharedMemorySize, 180000);
    k_gemm<<<N_NODES / TILE_N, 320, 44448 * sizeof(float)>>>(
        W0, b0, W1, b1, W2, b2, out);
}